// round 7
// baseline (speedup 1.0000x reference)
#include <cuda_runtime.h>
#include <math.h>

#define L 512
#define NCON 20
#define INV_TEMP (1.0f / 0.07f)
#define MAXROWS 32768
#define RP_BLOCKS 592   // 4 x 148; all co-resident (<=8 blocks/SM by warp limit)
#define RP_THREADS 256

// scratch (device globals; no allocation allowed)
__device__ int   g_cnt0[MAXROWS];            // histogram of sz_idx (zeroed each run, phase A)
__device__ int   g_cnt1[MAXROWS];            // histogram of nsz_idx
__device__ float g_pB[RP_BLOCKS];            // per-block partials
__device__ unsigned int g_fin = 0;           // finalize counter (reset by last block)
__device__ volatile unsigned int g_barcnt = 0;  // grid-barrier arrival count
__device__ volatile unsigned int g_gen = 0;     // grid-barrier generation (monotonic)

// Generation-based grid barrier. Safe because the whole grid is resident in
// wave 1 (592 blocks, tiny smem/regs). gen is read BEFORE arrival; releaser
// resets the counter before bumping gen, so reuse is race-free.
__device__ __forceinline__ void grid_barrier(unsigned int nblocks) {
    __syncthreads();
    if (threadIdx.x == 0) {
        unsigned int gen = g_gen;
        __threadfence();
        unsigned int t = atomicAdd((unsigned int*)&g_barcnt, 1u);
        if (t == nblocks - 1) {
            g_barcnt = 0;
            __threadfence();
            atomicAdd((unsigned int*)&g_gen, 1u);
        } else {
            while (g_gen == gen) __nanosleep(32);
        }
        __threadfence();
    }
    __syncthreads();
}

// ---------------------------------------------------------------------------
// Single fused kernel:
//  A) zero histograms (grid-strided) + build ebar in smem (overlapped)
//  B) int-atomic histogram of sz/nsz indices          (after barrier 1)
//  C) count-weighted rowpass, skipping unsampled rows (after barrier 2)
//  D) last-block fixed-order finalize -> out[0]
// loss = sum_r [ c0[r]*(log den0_r - d0_r*invn_r/tau)/Ns
//              + c1[r]*(log den1_r - d1_r*invn_r/tau)/Nn ]
// ---------------------------------------------------------------------------
__global__ void __launch_bounds__(RP_THREADS)
fused_kernel(const float* __restrict__ hg, int nrows,
             const float* __restrict__ corr,
             const float* __restrict__ all_emb,
             const int* __restrict__ Psz, int nPsz,
             const int* __restrict__ Pnsz, int nPnsz,
             const int* __restrict__ sz_idx, int Ns,
             const int* __restrict__ nsz_idx, int Nn,
             float invNs, float invNn, float* __restrict__ out) {
    __shared__ float se0[L];
    __shared__ float se1[L];
    __shared__ int sp[2][16];
    __shared__ float sw[8];
    __shared__ float sh[RP_THREADS];
    __shared__ bool is_last;

    int tid = threadIdx.x;
    int gthread = blockIdx.x * RP_THREADS + tid;
    int nthreads = gridDim.x * RP_THREADS;

    // --- phase A: zero histograms (1 element/thread) ---
    for (int i = gthread; i < nrows; i += nthreads) { g_cnt0[i] = 0; g_cnt1[i] = 0; }

    if (tid < nPsz)                    sp[0][tid]      = Psz[tid];
    if (tid >= 32 && tid - 32 < nPnsz) sp[1][tid - 32] = Pnsz[tid - 32];
    __syncthreads();

    // exclusion bitmasks (uniform)
    unsigned int mask0 = 0u, mask1 = 0u;
    for (int j = 0; j < nPsz; j++)  mask0 |= 1u << sp[0][j];
    for (int j = 0; j < nPnsz; j++) mask1 |= 1u << sp[1][j];

    // build ebar into smem (L2-hot all_emb; overlapped across blocks)
    for (int t = tid; t < L; t += RP_THREADS) {
        float s0 = 0.0f, s1 = 0.0f;
        for (int j = 0; j < nPsz; j++)  s0 += all_emb[sp[0][j] * L + t];
        for (int j = 0; j < nPnsz; j++) s1 += all_emb[sp[1][j] * L + t];
        se0[t] = s0 / (float)nPsz;
        se1[t] = s1 / (float)nPnsz;
    }

    grid_barrier(gridDim.x);

    // --- phase B: histograms (deterministic int atomics, spread addresses) ---
    for (int i = gthread; i < Ns; i += nthreads) atomicAdd(&g_cnt0[sz_idx[i]], 1);
    for (int i = gthread; i < Nn; i += nthreads) atomicAdd(&g_cnt1[nsz_idx[i]], 1);

    grid_barrier(gridDim.x);

    // --- phase C: count-weighted rowpass, one warp per row, skip c0|c1==0 ---
    int wg = gthread >> 5;
    int lane = tid & 31;
    int wib = tid >> 5;
    int nwarps = nthreads >> 5;
    const float4* e0p = reinterpret_cast<const float4*>(se0);
    const float4* e1p = reinterpret_cast<const float4*>(se1);
    bool act = lane < NCON;
    float w0m = (act && !((mask0 >> lane) & 1u)) ? 1.0f : 0.0f;
    float w1m = (act && !((mask1 >> lane) & 1u)) ? 1.0f : 0.0f;

    float acc = 0.0f;
    for (int row = wg; row < nrows; row += nwarps) {
        int c0 = g_cnt0[row];
        int c1 = g_cnt1[row];
        if ((c0 | c1) == 0) continue;   // unsampled row: zero contribution

        float e = act ? __expf(corr[row * NCON + lane] * INV_TEMP) : 0.0f;
        float den0 = e * w0m;
        float den1 = e * w1m;

        const float4* rp = reinterpret_cast<const float4*>(hg + (size_t)row * L);
        float ss = 0.0f, d0 = 0.0f, d1 = 0.0f;
#pragma unroll
        for (int it = 0; it < 4; it++) {
            int idx = it * 32 + lane;
            float4 v  = rp[idx];
            float4 e0 = e0p[idx];
            float4 e1 = e1p[idx];
            ss = fmaf(v.x, v.x, fmaf(v.y, v.y, fmaf(v.z, v.z, fmaf(v.w, v.w, ss))));
            d0 = fmaf(v.x, e0.x, fmaf(v.y, e0.y, fmaf(v.z, e0.z, fmaf(v.w, e0.w, d0))));
            d1 = fmaf(v.x, e1.x, fmaf(v.y, e1.y, fmaf(v.z, e1.z, fmaf(v.w, e1.w, d1))));
        }
#pragma unroll
        for (int o = 16; o > 0; o >>= 1) {
            ss   += __shfl_xor_sync(0xffffffffu, ss, o);
            d0   += __shfl_xor_sync(0xffffffffu, d0, o);
            d1   += __shfl_xor_sync(0xffffffffu, d1, o);
            den0 += __shfl_xor_sync(0xffffffffu, den0, o);
            den1 += __shfl_xor_sync(0xffffffffu, den1, o);
        }
        if (lane == 0) {
            float invn = 1.0f / fmaxf(sqrtf(ss), 1e-12f);
            acc += (float)c0 * invNs * (__logf(den0) - d0 * invn * INV_TEMP)
                 + (float)c1 * invNn * (__logf(den1) - d1 * invn * INV_TEMP);
        }
    }

    // --- phase D: block partial + last-block fixed-order finalize ---
    if (lane == 0) sw[wib] = acc;
    __syncthreads();
    if (tid == 0) {
        float s = 0.0f;
#pragma unroll
        for (int k = 0; k < 8; k++) s += sw[k];
        g_pB[blockIdx.x] = s;
        __threadfence();
        is_last = (atomicAdd(&g_fin, 1u) == gridDim.x - 1);
    }
    __syncthreads();

    if (is_last) {
        __threadfence();  // see all blocks' partials
        float a = 0.0f;
        for (int j = tid; j < RP_BLOCKS; j += RP_THREADS) a += g_pB[j];  // fixed order
        sh[tid] = a;
        __syncthreads();
        for (int s = 128; s > 0; s >>= 1) {
            if (tid < s) sh[tid] += sh[tid + s];
            __syncthreads();
        }
        if (tid == 0) { out[0] = sh[0]; g_fin = 0u; }
    }
}

extern "C" void kernel_launch(void* const* d_in, const int* in_sizes, int n_in,
                              void* d_out, int out_size) {
    const float* hg       = (const float*)d_in[0];
    const float* corr     = (const float*)d_in[1];
    const float* all_emb  = (const float*)d_in[2];
    const int*   sz_idx   = (const int*)d_in[3];
    const int*   nsz_idx  = (const int*)d_in[4];
    const int*   Psz_idx  = (const int*)d_in[5];
    const int*   Pnsz_idx = (const int*)d_in[6];
    float* out = (float*)d_out;

    int nrows = in_sizes[0] / L;          // 32768
    int Ns    = in_sizes[3];
    int Nn    = in_sizes[4];
    int nPsz  = in_sizes[5];
    int nPnsz = in_sizes[6];

    fused_kernel<<<RP_BLOCKS, RP_THREADS>>>(hg, nrows, corr, all_emb,
                                            Psz_idx, nPsz, Pnsz_idx, nPnsz,
                                            sz_idx, Ns, nsz_idx, Nn,
                                            1.0f / (float)Ns, 1.0f / (float)Nn,
                                            out);
}

// round 8
// speedup vs baseline: 1.0769x; 1.0769x over previous
#include <cuda_runtime.h>
#include <math.h>

#define L 512
#define NCON 20
#define INV_TEMP (1.0f / 0.07f)
#define MAXROWS 32768
#define RP_BLOCKS 592   // grid-stride rowpass blocks
#define RP_THREADS 256

// scratch (device globals; no allocation allowed)
// cnt arrays are zero on first run (static init) and reset-on-consume by the
// rowpass, so every replay's histogram starts from all-zeros.
__device__ int   g_cnt0[MAXROWS];        // histogram of sz_idx
__device__ int   g_cnt1[MAXROWS];        // histogram of nsz_idx
__device__ float g_pB[RP_BLOCKS];        // rowpass per-block partials
__device__ unsigned int g_fin = 0;       // finalize counter (reset by last block)

// ---------------------------------------------------------------------------
// Kernel A: index histograms. Blocks [0,Bs) handle sz_idx, [Bs,Bs+Bn) nsz_idx.
// One coalesced idx load + one spread int atomic per thread. Deterministic.
// ---------------------------------------------------------------------------
__global__ void hist_kernel(const int* __restrict__ sz_idx, int Ns,
                            const int* __restrict__ nsz_idx, int Nn, int Bs) {
    int b = blockIdx.x;
    int branch = (b >= Bs) ? 1 : 0;
    int i = (branch ? (b - Bs) : b) * (int)blockDim.x + threadIdx.x;
    if (branch) {
        if (i < Nn) atomicAdd(&g_cnt1[nsz_idx[i]], 1);
    } else {
        if (i < Ns) atomicAdd(&g_cnt0[sz_idx[i]], 1);
    }
}

// ---------------------------------------------------------------------------
// Kernel B: grid-stride rowpass + count-weighted accumulation + finalize.
// Each block builds ebar_sz/ebar_nsz in smem (10 L2-hot concept rows,
// overlapped across blocks), then one warp per row:
//   term = c0*(log den0 - d0*invn/tau)/Ns + c1*(log den1 - d1*invn/tau)/Nn
// cnt entries are reset to 0 after consumption (ready for next replay).
// Last block does the fixed-order finalize and resets g_fin.
// ---------------------------------------------------------------------------
__global__ void __launch_bounds__(RP_THREADS)
rowpass_fin_kernel(const float* __restrict__ hg, int nrows,
                   const float* __restrict__ corr,
                   const float* __restrict__ all_emb,
                   const int* __restrict__ Psz, int nPsz,
                   const int* __restrict__ Pnsz, int nPnsz,
                   float invNs, float invNn, float* __restrict__ out) {
    __shared__ float se0[L];
    __shared__ float se1[L];
    __shared__ int sp[2][16];
    __shared__ float sw[8];
    __shared__ float sh[RP_THREADS];
    __shared__ bool is_last;

    int tid = threadIdx.x;

    if (tid < nPsz)                    sp[0][tid]      = Psz[tid];
    if (tid >= 32 && tid - 32 < nPnsz) sp[1][tid - 32] = Pnsz[tid - 32];
    __syncthreads();

    // exclusion bitmasks (uniform)
    unsigned int mask0 = 0u, mask1 = 0u;
    for (int j = 0; j < nPsz; j++)  mask0 |= 1u << sp[0][j];
    for (int j = 0; j < nPnsz; j++) mask1 |= 1u << sp[1][j];

    // build ebar into smem
    for (int t = tid; t < L; t += RP_THREADS) {
        float s0 = 0.0f, s1 = 0.0f;
        for (int j = 0; j < nPsz; j++)  s0 += all_emb[sp[0][j] * L + t];
        for (int j = 0; j < nPnsz; j++) s1 += all_emb[sp[1][j] * L + t];
        se0[t] = s0 / (float)nPsz;
        se1[t] = s1 / (float)nPnsz;
    }
    __syncthreads();

    int wg   = (blockIdx.x * RP_THREADS + tid) >> 5;
    int lane = tid & 31;
    int wib  = tid >> 5;
    int nwarps = (gridDim.x * RP_THREADS) >> 5;
    const float4* e0p = reinterpret_cast<const float4*>(se0);
    const float4* e1p = reinterpret_cast<const float4*>(se1);
    bool act = lane < NCON;
    float w0m = (act && !((mask0 >> lane) & 1u)) ? 1.0f : 0.0f;
    float w1m = (act && !((mask1 >> lane) & 1u)) ? 1.0f : 0.0f;

    float acc = 0.0f;
    for (int row = wg; row < nrows; row += nwarps) {
        // counts (broadcast load), then reset-on-consume
        int c0 = g_cnt0[row];
        int c1 = g_cnt1[row];
        if (lane == 0 && (c0 | c1)) { g_cnt0[row] = 0; g_cnt1[row] = 0; }

        float e = act ? __expf(corr[row * NCON + lane] * INV_TEMP) : 0.0f;
        float den0 = e * w0m;
        float den1 = e * w1m;

        const float4* rp = reinterpret_cast<const float4*>(hg + (size_t)row * L);
        float ss = 0.0f, d0 = 0.0f, d1 = 0.0f;
#pragma unroll
        for (int it = 0; it < 4; it++) {
            int idx = it * 32 + lane;
            float4 v  = rp[idx];
            float4 e0 = e0p[idx];
            float4 e1 = e1p[idx];
            ss = fmaf(v.x, v.x, fmaf(v.y, v.y, fmaf(v.z, v.z, fmaf(v.w, v.w, ss))));
            d0 = fmaf(v.x, e0.x, fmaf(v.y, e0.y, fmaf(v.z, e0.z, fmaf(v.w, e0.w, d0))));
            d1 = fmaf(v.x, e1.x, fmaf(v.y, e1.y, fmaf(v.z, e1.z, fmaf(v.w, e1.w, d1))));
        }
#pragma unroll
        for (int o = 16; o > 0; o >>= 1) {
            ss   += __shfl_xor_sync(0xffffffffu, ss, o);
            d0   += __shfl_xor_sync(0xffffffffu, d0, o);
            d1   += __shfl_xor_sync(0xffffffffu, d1, o);
            den0 += __shfl_xor_sync(0xffffffffu, den0, o);
            den1 += __shfl_xor_sync(0xffffffffu, den1, o);
        }
        if (lane == 0) {
            float invn = 1.0f / fmaxf(sqrtf(ss), 1e-12f);
            acc += (float)c0 * invNs * (__logf(den0) - d0 * invn * INV_TEMP)
                 + (float)c1 * invNn * (__logf(den1) - d1 * invn * INV_TEMP);
        }
    }

    // block partial + last-block fixed-order finalize
    if (lane == 0) sw[wib] = acc;
    __syncthreads();
    if (tid == 0) {
        float s = 0.0f;
#pragma unroll
        for (int k = 0; k < 8; k++) s += sw[k];
        g_pB[blockIdx.x] = s;
        __threadfence();
        is_last = (atomicAdd(&g_fin, 1u) == gridDim.x - 1);
    }
    __syncthreads();

    if (is_last) {
        __threadfence();  // see all blocks' partials
        float a = 0.0f;
        for (int j = tid; j < RP_BLOCKS; j += RP_THREADS) a += g_pB[j];  // fixed order
        sh[tid] = a;
        __syncthreads();
        for (int s = 128; s > 0; s >>= 1) {
            if (tid < s) sh[tid] += sh[tid + s];
            __syncthreads();
        }
        if (tid == 0) { out[0] = sh[0]; g_fin = 0u; }
    }
}

extern "C" void kernel_launch(void* const* d_in, const int* in_sizes, int n_in,
                              void* d_out, int out_size) {
    const float* hg       = (const float*)d_in[0];
    const float* corr     = (const float*)d_in[1];
    const float* all_emb  = (const float*)d_in[2];
    const int*   sz_idx   = (const int*)d_in[3];
    const int*   nsz_idx  = (const int*)d_in[4];
    const int*   Psz_idx  = (const int*)d_in[5];
    const int*   Pnsz_idx = (const int*)d_in[6];
    float* out = (float*)d_out;

    int nrows = in_sizes[0] / L;          // 32768
    int Ns    = in_sizes[3];
    int Nn    = in_sizes[4];
    int nPsz  = in_sizes[5];
    int nPnsz = in_sizes[6];

    int Bs = (Ns + 255) / 256;
    int Bn = (Nn + 255) / 256;
    hist_kernel<<<Bs + Bn, 256>>>(sz_idx, Ns, nsz_idx, Nn, Bs);

    rowpass_fin_kernel<<<RP_BLOCKS, RP_THREADS>>>(hg, nrows, corr, all_emb,
                                                  Psz_idx, nPsz, Pnsz_idx, nPnsz,
                                                  1.0f / (float)Ns, 1.0f / (float)Nn,
                                                  out);
}